// round 2
// baseline (speedup 1.0000x reference)
#include <cuda_runtime.h>
#include <cstdint>
#include <cstddef>

// Problem constants
#define BB  4
#define SS  2048
#define CC  128
#define HH  8
#define DK_ 64
#define DV_ 64
#define KW  3

// Scratch (device globals — no allocation allowed)
__device__ float g_q [BB * HH * SS * DK_];   // (b,h,s,d)
__device__ float g_k [BB * HH * SS * DK_];   // (b,h,s,d)
__device__ float g_v [BB * HH * SS * DV_];   // (b,h,s,d)
__device__ float g_o1[BB * SS * HH * DV_];   // (b,s,h,d) == out2 rows (8192 x 512)

// ---------------------------------------------------------------------------
// K1: causal conv projections for Q and K.
// y[b,s,o] = sum_{t<3} sum_c x[b,s-2+t,c] * w[o,c,t] + bias[o]
// GEMM: M=64 s-tile, N=64 o-tile, K=384 (im2col via smem window).
// grid = (o_tile 16, s_tile 32, b 4), block = 256 (16x16, 4x4 per thread)
// ---------------------------------------------------------------------------
__global__ __launch_bounds__(256) void qk_conv_kernel(
    const float* __restrict__ x,
    const float* __restrict__ wq, const float* __restrict__ bq,
    const float* __restrict__ wk, const float* __restrict__ bk)
{
    __shared__ __align__(16) float xs[66][CC + 4];   // rows s0-2 .. s0+63
    __shared__ __align__(16) float ws[32][64];

    const int tid = threadIdx.x;
    const int tx = tid & 15, ty = tid >> 4;
    const int o0 = blockIdx.x * 64;
    const int s0 = blockIdx.y * 64;
    const int b  = blockIdx.z;

    for (int i = tid; i < 66 * CC; i += 256) {
        int r = i / CC, c = i % CC;
        int s = s0 - 2 + r;
        xs[r][c] = (s >= 0) ? x[((size_t)b * SS + s) * CC + c] : 0.f;
    }

    float acc[4][4] = {};

    for (int kc = 0; kc < KW * CC; kc += 32) {
        __syncthreads();
        const int t = kc >> 7;          // chunk never crosses a tap boundary
        const int cbase = kc & 127;
        for (int i = tid; i < 32 * 64; i += 256) {
            int kl = i >> 6, ol = i & 63;
            int o = o0 + ol, c = cbase + kl;
            ws[kl][ol] = (o < 512)
                ? wq[((size_t)o * CC + c) * KW + t]
                : wk[((size_t)(o - 512) * CC + c) * KW + t];
        }
        __syncthreads();
        #pragma unroll
        for (int kl = 0; kl < 32; kl++) {
            const int c = cbase + kl;
            float a0 = xs[ty * 4 + 0 + t][c];
            float a1 = xs[ty * 4 + 1 + t][c];
            float a2 = xs[ty * 4 + 2 + t][c];
            float a3 = xs[ty * 4 + 3 + t][c];
            float4 b4 = *(const float4*)&ws[kl][tx * 4];
            acc[0][0] += a0 * b4.x; acc[0][1] += a0 * b4.y; acc[0][2] += a0 * b4.z; acc[0][3] += a0 * b4.w;
            acc[1][0] += a1 * b4.x; acc[1][1] += a1 * b4.y; acc[1][2] += a1 * b4.z; acc[1][3] += a1 * b4.w;
            acc[2][0] += a2 * b4.x; acc[2][1] += a2 * b4.y; acc[2][2] += a2 * b4.z; acc[2][3] += a2 * b4.w;
            acc[3][0] += a3 * b4.x; acc[3][1] += a3 * b4.y; acc[3][2] += a3 * b4.z; acc[3][3] += a3 * b4.w;
        }
    }

    #pragma unroll
    for (int j = 0; j < 4; j++) {
        const int o = o0 + tx * 4 + j;
        const bool isq = (o < 512);
        const int oo = isq ? o : o - 512;
        const float bias = isq ? bq[oo] : bk[oo];
        const int h = oo >> 6, d = oo & 63;
        float* dst = isq ? g_q : g_k;
        #pragma unroll
        for (int i = 0; i < 4; i++) {
            const int s = s0 + ty * 4 + i;
            dst[(((size_t)b * HH + h) * SS + s) * DK_ + d] = acc[i][j] + bias;
        }
    }
}

// ---------------------------------------------------------------------------
// K2: V = relu(x @ wv^T + bv), stored as (b,h,s,d).
// grid = (o_tile 8, s_tile 128), block 256
// ---------------------------------------------------------------------------
__global__ __launch_bounds__(256) void v_proj_kernel(
    const float* __restrict__ x,
    const float* __restrict__ wv, const float* __restrict__ bv)
{
    __shared__ __align__(16) float Xs[32][68];
    __shared__ __align__(16) float Ws[32][68];
    const int tid = threadIdx.x, tx = tid & 15, ty = tid >> 4;
    const int o0 = blockIdx.x * 64;
    const int s0 = blockIdx.y * 64;   // global over B*S

    float acc[4][4] = {};

    for (int kc = 0; kc < CC; kc += 32) {
        __syncthreads();
        for (int i = tid; i < 2048; i += 256) {
            int kl = i & 31, r = i >> 5;
            Xs[kl][r] = x [((size_t)(s0 + r)) * CC + kc + kl];
            Ws[kl][r] = wv[((size_t)(o0 + r)) * CC + kc + kl];
        }
        __syncthreads();
        #pragma unroll
        for (int kk = 0; kk < 32; kk++) {
            float4 a4 = *(const float4*)&Xs[kk][ty * 4];
            float4 b4 = *(const float4*)&Ws[kk][tx * 4];
            acc[0][0] += a4.x * b4.x; acc[0][1] += a4.x * b4.y; acc[0][2] += a4.x * b4.z; acc[0][3] += a4.x * b4.w;
            acc[1][0] += a4.y * b4.x; acc[1][1] += a4.y * b4.y; acc[1][2] += a4.y * b4.z; acc[1][3] += a4.y * b4.w;
            acc[2][0] += a4.z * b4.x; acc[2][1] += a4.z * b4.y; acc[2][2] += a4.z * b4.z; acc[2][3] += a4.z * b4.w;
            acc[3][0] += a4.w * b4.x; acc[3][1] += a4.w * b4.y; acc[3][2] += a4.w * b4.z; acc[3][3] += a4.w * b4.w;
        }
    }

    #pragma unroll
    for (int j = 0; j < 4; j++) {
        const int o = o0 + tx * 4 + j;
        const float bias = bv[o];
        const int h = o >> 6, d = o & 63;
        #pragma unroll
        for (int i = 0; i < 4; i++) {
            const int s = s0 + ty * 4 + i;
            const int bb = s >> 11, sl = s & (SS - 1);
            g_v[(((size_t)bb * HH + h) * SS + sl) * DV_ + d] = fmaxf(acc[i][j] + bias, 0.f);
        }
    }
}

// ---------------------------------------------------------------------------
// K3: logits = Q K^T / 8 for lower-triangle tiles only, written raw into the
// score output region (normalized in place by K4).
// grid = (kt 32, qt 32, bh 32), block 256
// ---------------------------------------------------------------------------
__global__ __launch_bounds__(256) void logits_kernel(float* __restrict__ score)
{
    const int kt = blockIdx.x, qt = blockIdx.y, bh = blockIdx.z;
    if (kt > qt) return;
    __shared__ __align__(16) float Qs[64][68];   // [d][q]
    __shared__ __align__(16) float Ks[64][68];   // [d][k]
    const int tid = threadIdx.x, tx = tid & 15, ty = tid >> 4;

    for (int i = tid; i < 4096; i += 256) {
        int r = i >> 6, d = i & 63;
        Qs[d][r] = g_q[((size_t)bh * SS + qt * 64 + r) * DK_ + d];
        Ks[d][r] = g_k[((size_t)bh * SS + kt * 64 + r) * DK_ + d];
    }
    __syncthreads();

    float acc[4][4] = {};
    #pragma unroll
    for (int kk = 0; kk < 64; kk++) {
        float4 a4 = *(const float4*)&Qs[kk][ty * 4];
        float4 b4 = *(const float4*)&Ks[kk][tx * 4];
        acc[0][0] += a4.x * b4.x; acc[0][1] += a4.x * b4.y; acc[0][2] += a4.x * b4.z; acc[0][3] += a4.x * b4.w;
        acc[1][0] += a4.y * b4.x; acc[1][1] += a4.y * b4.y; acc[1][2] += a4.y * b4.z; acc[1][3] += a4.y * b4.w;
        acc[2][0] += a4.z * b4.x; acc[2][1] += a4.z * b4.y; acc[2][2] += a4.z * b4.z; acc[2][3] += a4.z * b4.w;
        acc[3][0] += a4.w * b4.x; acc[3][1] += a4.w * b4.y; acc[3][2] += a4.w * b4.z; acc[3][3] += a4.w * b4.w;
    }

    #pragma unroll
    for (int i = 0; i < 4; i++) {
        const int q = qt * 64 + ty * 4 + i;
        #pragma unroll
        for (int j = 0; j < 4; j++) {
            const int k = kt * 64 + tx * 4 + j;
            score[((size_t)bh * SS + q) * SS + k] = acc[i][j] * 0.125f;
        }
    }
}

// ---------------------------------------------------------------------------
// K4: in-place row softmax over the causal prefix; writes zeros above the
// diagonal and for padded query rows. One block (256 thr) per row.
// ---------------------------------------------------------------------------
__global__ __launch_bounds__(256) void softmax_kernel(
    float* __restrict__ score, const int* __restrict__ length)
{
    const int row = blockIdx.x;            // 0 .. B*H*S-1
    const int q  = row & (SS - 1);
    const int bh = row >> 11;
    const int b  = bh >> 3;
    float* rp = score + (size_t)row * SS;
    const int tid = threadIdx.x;
    __shared__ float red[8];
    __shared__ float bc;

    if (q >= length[b]) {
        for (int k = tid; k < SS; k += 256) rp[k] = 0.f;
        return;
    }

    float v[8];
    float m = -1e30f;
    #pragma unroll
    for (int i = 0; i < 8; i++) {
        int k = tid + i * 256;
        v[i] = (k <= q) ? rp[k] : -1e30f;
        m = fmaxf(m, v[i]);
    }
    #pragma unroll
    for (int o = 16; o; o >>= 1) m = fmaxf(m, __shfl_xor_sync(0xffffffffu, m, o));
    if ((tid & 31) == 0) red[tid >> 5] = m;
    __syncthreads();
    if (tid == 0) {
        float t = red[0];
        #pragma unroll
        for (int w = 1; w < 8; w++) t = fmaxf(t, red[w]);
        bc = t;
    }
    __syncthreads();
    m = bc;

    float e[8];
    float sum = 0.f;
    #pragma unroll
    for (int i = 0; i < 8; i++) {
        int k = tid + i * 256;
        e[i] = (k <= q) ? __expf(v[i] - m) : 0.f;
        sum += e[i];
    }
    #pragma unroll
    for (int o = 16; o; o >>= 1) sum += __shfl_xor_sync(0xffffffffu, sum, o);
    __syncthreads();
    if ((tid & 31) == 0) red[tid >> 5] = sum;
    __syncthreads();
    if (tid == 0) {
        float t = 0.f;
        #pragma unroll
        for (int w = 0; w < 8; w++) t += red[w];
        bc = t;
    }
    __syncthreads();
    const float inv = 1.f / bc;
    #pragma unroll
    for (int i = 0; i < 8; i++) {
        int k = tid + i * 256;
        rp[k] = e[i] * inv;      // zeros for k > q
    }
}

// ---------------------------------------------------------------------------
// K5: out1 = P @ V (triangle-aware K loop). Result stored (b,s,h,d).
// grid = (qt 32, bh 32), block 256
// ---------------------------------------------------------------------------
__global__ __launch_bounds__(256) void pv_kernel(const float* __restrict__ score)
{
    const int qt = blockIdx.x, bh = blockIdx.y;
    const int b = bh >> 3, h = bh & 7;
    __shared__ __align__(16) float Ps[64][68];   // [k][q]
    __shared__ __align__(16) float Vs[64][68];   // [k][d]
    const int tid = threadIdx.x, tx = tid & 15, ty = tid >> 4;

    float acc[4][4] = {};

    for (int kt = 0; kt <= qt; kt++) {
        __syncthreads();
        for (int i = tid; i < 4096; i += 256) {
            int r = i >> 6, c = i & 63;
            Ps[c][r] = score[((size_t)bh * SS + qt * 64 + r) * SS + kt * 64 + c];
            Vs[r][c] = g_v[((size_t)bh * SS + kt * 64 + r) * DV_ + c];
        }
        __syncthreads();
        #pragma unroll
        for (int kk = 0; kk < 64; kk++) {
            float4 a4 = *(const float4*)&Ps[kk][ty * 4];
            float4 b4 = *(const float4*)&Vs[kk][tx * 4];
            acc[0][0] += a4.x * b4.x; acc[0][1] += a4.x * b4.y; acc[0][2] += a4.x * b4.z; acc[0][3] += a4.x * b4.w;
            acc[1][0] += a4.y * b4.x; acc[1][1] += a4.y * b4.y; acc[1][2] += a4.y * b4.z; acc[1][3] += a4.y * b4.w;
            acc[2][0] += a4.z * b4.x; acc[2][1] += a4.z * b4.y; acc[2][2] += a4.z * b4.z; acc[2][3] += a4.z * b4.w;
            acc[3][0] += a4.w * b4.x; acc[3][1] += a4.w * b4.y; acc[3][2] += a4.w * b4.z; acc[3][3] += a4.w * b4.w;
        }
    }

    #pragma unroll
    for (int j = 0; j < 4; j++) {
        const int d = tx * 4 + j;
        #pragma unroll
        for (int i = 0; i < 4; i++) {
            const int s = qt * 64 + ty * 4 + i;
            g_o1[(((size_t)b * SS + s) * HH + h) * DV_ + d] = acc[i][j];
        }
    }
}

// ---------------------------------------------------------------------------
// K6: out3 = relu(out2 @ w1^T + b1) @ w2^T + b2 ; out2 rows are g_o1 (8192x512)
// grid = 128 (64 s per block), block 256
// ---------------------------------------------------------------------------
__global__ __launch_bounds__(256) void mlp_kernel(
    const float* __restrict__ w1, const float* __restrict__ b1,
    const float* __restrict__ w2, const float* __restrict__ b2,
    float* __restrict__ out3)
{
    __shared__ __align__(16) float Os [32][68];   // [kl][s]
    __shared__ __align__(16) float W1s[32][68];   // [kl][j]
    __shared__ __align__(16) float hids[64][68];  // [s][j]
    const int tid = threadIdx.x, tx = tid & 15, ty = tid >> 4;
    const int s0 = blockIdx.x * 64;

    float acc[4][4] = {};

    for (int kc = 0; kc < 512; kc += 32) {
        __syncthreads();
        for (int i = tid; i < 2048; i += 256) {
            int kl = i & 31, r = i >> 5;
            Os [kl][r] = g_o1[((size_t)(s0 + r)) * 512 + kc + kl];
            W1s[kl][r] = w1 [((size_t)r) * 512 + kc + kl];
        }
        __syncthreads();
        #pragma unroll
        for (int kk = 0; kk < 32; kk++) {
            float4 a4 = *(const float4*)&Os [kk][ty * 4];
            float4 b4 = *(const float4*)&W1s[kk][tx * 4];
            acc[0][0] += a4.x * b4.x; acc[0][1] += a4.x * b4.y; acc[0][2] += a4.x * b4.z; acc[0][3] += a4.x * b4.w;
            acc[1][0] += a4.y * b4.x; acc[1][1] += a4.y * b4.y; acc[1][2] += a4.y * b4.z; acc[1][3] += a4.y * b4.w;
            acc[2][0] += a4.z * b4.x; acc[2][1] += a4.z * b4.y; acc[2][2] += a4.z * b4.z; acc[2][3] += a4.z * b4.w;
            acc[3][0] += a4.w * b4.x; acc[3][1] += a4.w * b4.y; acc[3][2] += a4.w * b4.z; acc[3][3] += a4.w * b4.w;
        }
    }

    #pragma unroll
    for (int i = 0; i < 4; i++)
        #pragma unroll
        for (int j = 0; j < 4; j++)
            hids[ty * 4 + i][tx * 4 + j] = fmaxf(acc[i][j] + b1[tx * 4 + j], 0.f);
    __syncthreads();

    if (tid < 64) {
        float sum = 0.f;
        #pragma unroll 8
        for (int j = 0; j < 64; j++) sum += hids[tid][j] * w2[j];
        out3[s0 + tid] = sum + b2[0];
    }
}

// ---------------------------------------------------------------------------
extern "C" void kernel_launch(void* const* d_in, const int* in_sizes, int n_in,
                              void* d_out, int out_size)
{
    const float* x      = (const float*)d_in[0];
    const int*   length = (const int*)  d_in[1];
    const float* wq     = (const float*)d_in[2];
    const float* bq     = (const float*)d_in[3];
    const float* wk     = (const float*)d_in[4];
    const float* bk     = (const float*)d_in[5];
    const float* wv     = (const float*)d_in[6];
    const float* bv     = (const float*)d_in[7];
    const float* w1     = (const float*)d_in[8];
    const float* b1     = (const float*)d_in[9];
    const float* w2     = (const float*)d_in[10];
    const float* b2     = (const float*)d_in[11];

    float* out   = (float*)d_out;
    float* out3  = out;                       // (B,S,1) = 8192 elements
    float* score = out + (size_t)BB * SS;     // (B,H,S,S)

    qk_conv_kernel<<<dim3(16, 32, BB), 256>>>(x, wq, bq, wk, bk);
    v_proj_kernel <<<dim3(8, 128),     256>>>(x, wv, bv);
    logits_kernel <<<dim3(32, 32, 32), 256>>>(score);
    softmax_kernel<<<BB * HH * SS,     256>>>(score, length);
    pv_kernel     <<<dim3(32, 32),     256>>>(score);
    mlp_kernel    <<<128,              256>>>(w1, b1, w2, b2, out3);
}

// round 3
// speedup vs baseline: 1.0102x; 1.0102x over previous
#include <cuda_runtime.h>
#include <cstdint>
#include <cstddef>

// Problem constants
#define BB  4
#define SS  2048
#define CC  128
#define HH  8
#define DK_ 64
#define DV_ 64
#define KW  3

typedef unsigned long long u64;

// Scratch (device globals — no allocation allowed)
__device__ float g_q [BB * HH * SS * DK_];   // (b,h,s,d)
__device__ float g_k [BB * HH * SS * DK_];   // (b,h,s,d)
__device__ float g_v [BB * HH * SS * DV_];   // (b,h,s,d)
__device__ float g_o1[BB * SS * HH * DV_];   // (b,s,h,d) == out2 rows (8192 x 512)

// Packed fp32x2 helpers (sm_103a: fma.rn.f32x2 = 2 FMA per FMA-pipe slot)
__device__ __forceinline__ void fma2(u64& d, u64 a, u64 b) {
    asm("fma.rn.f32x2 %0, %1, %2, %0;" : "+l"(d) : "l"(a), "l"(b));
}
__device__ __forceinline__ u64 pack2(float x) {
    u64 r; asm("mov.b64 %0, {%1, %1};" : "=l"(r) : "f"(x)); return r;
}
__device__ __forceinline__ float2 unpack2(u64 v) {
    float2 r; asm("mov.b64 {%0, %1}, %2;" : "=f"(r.x), "=f"(r.y) : "l"(v)); return r;
}

// ---------------------------------------------------------------------------
// K1: causal conv projections for Q and K.
// y[b,s,o] = sum_{t<3} sum_c x[b,s-2+t,c] * w[o,c,t] + bias[o]
// GEMM: M=64 s-tile, N=64 o-tile, K=384 (im2col via smem window).
// grid = (o_tile 16, s_tile 32, b 4), block = 256 (16x16, 4x4 per thread)
// ---------------------------------------------------------------------------
__global__ __launch_bounds__(256) void qk_conv_kernel(
    const float* __restrict__ x,
    const float* __restrict__ wq, const float* __restrict__ bq,
    const float* __restrict__ wk, const float* __restrict__ bk)
{
    __shared__ __align__(16) float xs[66][CC + 4];   // rows s0-2 .. s0+63
    __shared__ __align__(16) float ws[32][64];

    const int tid = threadIdx.x;
    const int tx = tid & 15, ty = tid >> 4;
    const int o0 = blockIdx.x * 64;
    const int s0 = blockIdx.y * 64;
    const int b  = blockIdx.z;

    for (int i = tid; i < 66 * CC; i += 256) {
        int r = i / CC, c = i % CC;
        int s = s0 - 2 + r;
        xs[r][c] = (s >= 0) ? x[((size_t)b * SS + s) * CC + c] : 0.f;
    }

    u64 acc[4][2] = {};

    for (int kc = 0; kc < KW * CC; kc += 32) {
        __syncthreads();
        const int t = kc >> 7;          // chunk never crosses a tap boundary
        const int cbase = kc & 127;
        for (int i = tid; i < 32 * 64; i += 256) {
            int kl = i >> 6, ol = i & 63;
            int o = o0 + ol, c = cbase + kl;
            ws[kl][ol] = (o < 512)
                ? wq[((size_t)o * CC + c) * KW + t]
                : wk[((size_t)(o - 512) * CC + c) * KW + t];
        }
        __syncthreads();
        #pragma unroll
        for (int kl = 0; kl < 32; kl++) {
            const int c = cbase + kl;
            u64 a0 = pack2(xs[ty * 4 + 0 + t][c]);
            u64 a1 = pack2(xs[ty * 4 + 1 + t][c]);
            u64 a2 = pack2(xs[ty * 4 + 2 + t][c]);
            u64 a3 = pack2(xs[ty * 4 + 3 + t][c]);
            ulonglong2 b2 = *(const ulonglong2*)&ws[kl][tx * 4];
            fma2(acc[0][0], a0, b2.x); fma2(acc[0][1], a0, b2.y);
            fma2(acc[1][0], a1, b2.x); fma2(acc[1][1], a1, b2.y);
            fma2(acc[2][0], a2, b2.x); fma2(acc[2][1], a2, b2.y);
            fma2(acc[3][0], a3, b2.x); fma2(acc[3][1], a3, b2.y);
        }
    }

    // Whole 64-wide o-tile lives in one head of one of {Q, K}
    const bool isq = (o0 < 512);
    const int obase = isq ? o0 : o0 - 512;
    const int h = obase >> 6;
    float* dst = isq ? g_q : g_k;
    const float4 bias4 = *(const float4*)&(isq ? bq : bk)[obase + tx * 4];

    #pragma unroll
    for (int i = 0; i < 4; i++) {
        const int s = s0 + ty * 4 + i;
        float2 p0 = unpack2(acc[i][0]), p1 = unpack2(acc[i][1]);
        float4 r = { p0.x + bias4.x, p0.y + bias4.y, p1.x + bias4.z, p1.y + bias4.w };
        *(float4*)&dst[(((size_t)b * HH + h) * SS + s) * DK_ + tx * 4] = r;
    }
}

// ---------------------------------------------------------------------------
// K2: V = relu(x @ wv^T + bv), stored as (b,h,s,d).
// grid = (o_tile 8, s_tile 128), block 256
// ---------------------------------------------------------------------------
__global__ __launch_bounds__(256) void v_proj_kernel(
    const float* __restrict__ x,
    const float* __restrict__ wv, const float* __restrict__ bv)
{
    __shared__ __align__(16) float Xs[32][68];
    __shared__ __align__(16) float Ws[32][68];
    const int tid = threadIdx.x, tx = tid & 15, ty = tid >> 4;
    const int o0 = blockIdx.x * 64;
    const int s0 = blockIdx.y * 64;   // global over B*S

    u64 acc[4][2] = {};

    for (int kc = 0; kc < CC; kc += 32) {
        __syncthreads();
        for (int i = tid; i < 2048; i += 256) {
            int kl = i & 31, r = i >> 5;
            Xs[kl][r] = x [((size_t)(s0 + r)) * CC + kc + kl];
            Ws[kl][r] = wv[((size_t)(o0 + r)) * CC + kc + kl];
        }
        __syncthreads();
        #pragma unroll
        for (int kk = 0; kk < 32; kk++) {
            float4 a4 = *(const float4*)&Xs[kk][ty * 4];
            ulonglong2 b2 = *(const ulonglong2*)&Ws[kk][tx * 4];
            u64 a0 = pack2(a4.x), a1 = pack2(a4.y), a2 = pack2(a4.z), a3 = pack2(a4.w);
            fma2(acc[0][0], a0, b2.x); fma2(acc[0][1], a0, b2.y);
            fma2(acc[1][0], a1, b2.x); fma2(acc[1][1], a1, b2.y);
            fma2(acc[2][0], a2, b2.x); fma2(acc[2][1], a2, b2.y);
            fma2(acc[3][0], a3, b2.x); fma2(acc[3][1], a3, b2.y);
        }
    }

    const int h = o0 >> 6;
    const float4 bias4 = *(const float4*)&bv[o0 + tx * 4];
    #pragma unroll
    for (int i = 0; i < 4; i++) {
        const int s = s0 + ty * 4 + i;
        const int bb = s >> 11, sl = s & (SS - 1);
        float2 p0 = unpack2(acc[i][0]), p1 = unpack2(acc[i][1]);
        float4 r = { fmaxf(p0.x + bias4.x, 0.f), fmaxf(p0.y + bias4.y, 0.f),
                     fmaxf(p1.x + bias4.z, 0.f), fmaxf(p1.y + bias4.w, 0.f) };
        *(float4*)&g_v[(((size_t)bb * HH + h) * SS + sl) * DV_ + tx * 4] = r;
    }
}

// ---------------------------------------------------------------------------
// K3: logits = Q K^T / 8 for lower-triangle tiles only, written raw into the
// score output region (normalized in place by K4).
// grid = (kt 32, qt 32, bh 32), block 256
// ---------------------------------------------------------------------------
__global__ __launch_bounds__(256) void logits_kernel(float* __restrict__ score)
{
    const int kt = blockIdx.x, qt = blockIdx.y, bh = blockIdx.z;
    if (kt > qt) return;
    __shared__ __align__(16) float Qs[64][68];   // [d][q]
    __shared__ __align__(16) float Ks[64][68];   // [d][k]
    const int tid = threadIdx.x, tx = tid & 15, ty = tid >> 4;

    for (int i = tid; i < 4096; i += 256) {
        int r = i >> 6, d = i & 63;
        Qs[d][r] = g_q[((size_t)bh * SS + qt * 64 + r) * DK_ + d];
        Ks[d][r] = g_k[((size_t)bh * SS + kt * 64 + r) * DK_ + d];
    }
    __syncthreads();

    u64 acc[4][2] = {};
    #pragma unroll
    for (int kk = 0; kk < 64; kk++) {
        float4 a4 = *(const float4*)&Qs[kk][ty * 4];
        ulonglong2 b2 = *(const ulonglong2*)&Ks[kk][tx * 4];
        u64 a0 = pack2(a4.x), a1 = pack2(a4.y), a2 = pack2(a4.z), a3 = pack2(a4.w);
        fma2(acc[0][0], a0, b2.x); fma2(acc[0][1], a0, b2.y);
        fma2(acc[1][0], a1, b2.x); fma2(acc[1][1], a1, b2.y);
        fma2(acc[2][0], a2, b2.x); fma2(acc[2][1], a2, b2.y);
        fma2(acc[3][0], a3, b2.x); fma2(acc[3][1], a3, b2.y);
    }

    #pragma unroll
    for (int i = 0; i < 4; i++) {
        const int q = qt * 64 + ty * 4 + i;
        float2 p0 = unpack2(acc[i][0]), p1 = unpack2(acc[i][1]);
        float4 r = { p0.x * 0.125f, p0.y * 0.125f, p1.x * 0.125f, p1.y * 0.125f };
        *(float4*)&score[((size_t)bh * SS + q) * SS + kt * 64 + tx * 4] = r;
    }
}

// ---------------------------------------------------------------------------
// K4: in-place row softmax over the causal prefix; writes zeros above the
// diagonal and for padded query rows. One block (256 thr) per row.
// ---------------------------------------------------------------------------
__global__ __launch_bounds__(256) void softmax_kernel(
    float* __restrict__ score, const int* __restrict__ length)
{
    const int row = blockIdx.x;            // 0 .. B*H*S-1
    const int q  = row & (SS - 1);
    const int bh = row >> 11;
    const int b  = bh >> 3;
    float* rp = score + (size_t)row * SS;
    const int tid = threadIdx.x;
    __shared__ float red[8];
    __shared__ float bc;

    if (q >= length[b]) {
        for (int k = tid; k < SS; k += 256) rp[k] = 0.f;
        return;
    }

    float v[8];
    float m = -1e30f;
    #pragma unroll
    for (int i = 0; i < 8; i++) {
        int k = tid + i * 256;
        v[i] = (k <= q) ? rp[k] : -1e30f;
        m = fmaxf(m, v[i]);
    }
    #pragma unroll
    for (int o = 16; o; o >>= 1) m = fmaxf(m, __shfl_xor_sync(0xffffffffu, m, o));
    if ((tid & 31) == 0) red[tid >> 5] = m;
    __syncthreads();
    if (tid == 0) {
        float t = red[0];
        #pragma unroll
        for (int w = 1; w < 8; w++) t = fmaxf(t, red[w]);
        bc = t;
    }
    __syncthreads();
    m = bc;

    float e[8];
    float sum = 0.f;
    #pragma unroll
    for (int i = 0; i < 8; i++) {
        int k = tid + i * 256;
        e[i] = (k <= q) ? __expf(v[i] - m) : 0.f;
        sum += e[i];
    }
    #pragma unroll
    for (int o = 16; o; o >>= 1) sum += __shfl_xor_sync(0xffffffffu, sum, o);
    __syncthreads();
    if ((tid & 31) == 0) red[tid >> 5] = sum;
    __syncthreads();
    if (tid == 0) {
        float t = 0.f;
        #pragma unroll
        for (int w = 0; w < 8; w++) t += red[w];
        bc = t;
    }
    __syncthreads();
    const float inv = 1.f / bc;
    #pragma unroll
    for (int i = 0; i < 8; i++) {
        int k = tid + i * 256;
        rp[k] = e[i] * inv;      // zeros for k > q
    }
}

// ---------------------------------------------------------------------------
// K5: out1 = P @ V (triangle-aware K loop). Result stored (b,s,h,d).
// grid = (qt 32, bh 32), block 256
// ---------------------------------------------------------------------------
__global__ __launch_bounds__(256) void pv_kernel(const float* __restrict__ score)
{
    const int qt = blockIdx.x, bh = blockIdx.y;
    const int b = bh >> 3, h = bh & 7;
    __shared__ __align__(16) float Ps[64][68];   // [k][q]
    __shared__ __align__(16) float Vs[64][68];   // [k][d]
    const int tid = threadIdx.x, tx = tid & 15, ty = tid >> 4;

    u64 acc[4][2] = {};

    for (int kt = 0; kt <= qt; kt++) {
        __syncthreads();
        for (int i = tid; i < 4096; i += 256) {
            int r = i >> 6, c = i & 63;
            Ps[c][r] = score[((size_t)bh * SS + qt * 64 + r) * SS + kt * 64 + c];
            Vs[r][c] = g_v[((size_t)bh * SS + kt * 64 + r) * DV_ + c];
        }
        __syncthreads();
        #pragma unroll
        for (int kk = 0; kk < 64; kk++) {
            float4 a4 = *(const float4*)&Ps[kk][ty * 4];
            ulonglong2 b2 = *(const ulonglong2*)&Vs[kk][tx * 4];
            u64 a0 = pack2(a4.x), a1 = pack2(a4.y), a2 = pack2(a4.z), a3 = pack2(a4.w);
            fma2(acc[0][0], a0, b2.x); fma2(acc[0][1], a0, b2.y);
            fma2(acc[1][0], a1, b2.x); fma2(acc[1][1], a1, b2.y);
            fma2(acc[2][0], a2, b2.x); fma2(acc[2][1], a2, b2.y);
            fma2(acc[3][0], a3, b2.x); fma2(acc[3][1], a3, b2.y);
        }
    }

    #pragma unroll
    for (int i = 0; i < 4; i++) {
        const int s = qt * 64 + ty * 4 + i;
        float2 p0 = unpack2(acc[i][0]), p1 = unpack2(acc[i][1]);
        float4 r = { p0.x, p0.y, p1.x, p1.y };
        *(float4*)&g_o1[(((size_t)b * SS + s) * HH + h) * DV_ + tx * 4] = r;
    }
}

// ---------------------------------------------------------------------------
// K6: out3 = relu(out2 @ w1^T + b1) @ w2^T + b2 ; out2 rows are g_o1 (8192x512)
// grid = 128 (64 s per block), block 256
// ---------------------------------------------------------------------------
__global__ __launch_bounds__(256) void mlp_kernel(
    const float* __restrict__ w1, const float* __restrict__ b1,
    const float* __restrict__ w2, const float* __restrict__ b2,
    float* __restrict__ out3)
{
    __shared__ __align__(16) float Os [32][68];   // [kl][s]
    __shared__ __align__(16) float W1s[32][68];   // [kl][j]
    __shared__ __align__(16) float hids[64][68];  // [s][j]
    const int tid = threadIdx.x, tx = tid & 15, ty = tid >> 4;
    const int s0 = blockIdx.x * 64;

    u64 acc[4][2] = {};

    for (int kc = 0; kc < 512; kc += 32) {
        __syncthreads();
        for (int i = tid; i < 2048; i += 256) {
            int kl = i & 31, r = i >> 5;
            Os [kl][r] = g_o1[((size_t)(s0 + r)) * 512 + kc + kl];
            W1s[kl][r] = w1 [((size_t)r) * 512 + kc + kl];
        }
        __syncthreads();
        #pragma unroll
        for (int kk = 0; kk < 32; kk++) {
            float4 a4 = *(const float4*)&Os [kk][ty * 4];
            ulonglong2 b2 = *(const ulonglong2*)&W1s[kk][tx * 4];
            u64 a0 = pack2(a4.x), a1 = pack2(a4.y), a2 = pack2(a4.z), a3 = pack2(a4.w);
            fma2(acc[0][0], a0, b2.x); fma2(acc[0][1], a0, b2.y);
            fma2(acc[1][0], a1, b2.x); fma2(acc[1][1], a1, b2.y);
            fma2(acc[2][0], a2, b2.x); fma2(acc[2][1], a2, b2.y);
            fma2(acc[3][0], a3, b2.x); fma2(acc[3][1], a3, b2.y);
        }
    }

    const float4 b14 = *(const float4*)&b1[tx * 4];
    #pragma unroll
    for (int i = 0; i < 4; i++) {
        float2 p0 = unpack2(acc[i][0]), p1 = unpack2(acc[i][1]);
        float4 r = { fmaxf(p0.x + b14.x, 0.f), fmaxf(p0.y + b14.y, 0.f),
                     fmaxf(p1.x + b14.z, 0.f), fmaxf(p1.y + b14.w, 0.f) };
        *(float4*)&hids[ty * 4 + i][tx * 4] = r;
    }
    __syncthreads();

    if (tid < 64) {
        float sum = 0.f;
        #pragma unroll 8
        for (int j = 0; j < 64; j++) sum += hids[tid][j] * w2[j];
        out3[s0 + tid] = sum + b2[0];
    }
}

// ---------------------------------------------------------------------------
extern "C" void kernel_launch(void* const* d_in, const int* in_sizes, int n_in,
                              void* d_out, int out_size)
{
    const float* x      = (const float*)d_in[0];
    const int*   length = (const int*)  d_in[1];
    const float* wq     = (const float*)d_in[2];
    const float* bq     = (const float*)d_in[3];
    const float* wk     = (const float*)d_in[4];
    const float* bk     = (const float*)d_in[5];
    const float* wv     = (const float*)d_in[6];
    const float* bv     = (const float*)d_in[7];
    const float* w1     = (const float*)d_in[8];
    const float* b1     = (const float*)d_in[9];
    const float* w2     = (const float*)d_in[10];
    const float* b2     = (const float*)d_in[11];

    float* out   = (float*)d_out;
    float* out3  = out;                       // (B,S,1) = 8192 elements
    float* score = out + (size_t)BB * SS;     // (B,H,S,S)

    qk_conv_kernel<<<dim3(16, 32, BB), 256>>>(x, wq, bq, wk, bk);
    v_proj_kernel <<<dim3(8, 128),     256>>>(x, wv, bv);
    logits_kernel <<<dim3(32, 32, 32), 256>>>(score);
    softmax_kernel<<<BB * HH * SS,     256>>>(score, length);
    pv_kernel     <<<dim3(32, 32),     256>>>(score);
    mlp_kernel    <<<128,              256>>>(w1, b1, w2, b2, out3);
}

// round 4
// speedup vs baseline: 1.2107x; 1.1985x over previous
#include <cuda_runtime.h>
#include <cstdint>
#include <cstddef>

// Problem constants
#define BB  4
#define SS  2048
#define CC  128
#define HH  8
#define DK_ 64
#define DV_ 64
#define KW  3

typedef unsigned long long u64;

// Scratch (device globals — no allocation allowed)
__device__ float g_q [BB * HH * DK_ * SS];   // (b,h,d,s)  TRANSPOSED
__device__ float g_k [BB * HH * DK_ * SS];   // (b,h,d,s)  TRANSPOSED
__device__ float g_v [BB * HH * SS * DV_];   // (b,h,s,d)
__device__ float g_o1[BB * SS * HH * DV_];   // (b,s,h,d) == out2 rows (8192 x 512)
__device__ float g_wt[KW * CC * 1024];       // (t,c,o) transposed conv weights, o: [Q 512 | K 512]

// Packed fp32x2 helpers (sm_103a: fma.rn.f32x2 = 2 FMA per FMA-pipe slot)
__device__ __forceinline__ void fma2(u64& d, u64 a, u64 b) {
    asm("fma.rn.f32x2 %0, %1, %2, %0;" : "+l"(d) : "l"(a), "l"(b));
}
__device__ __forceinline__ u64 pack2(float x) {
    u64 r; asm("mov.b64 %0, {%1, %1};" : "=l"(r) : "f"(x)); return r;
}
__device__ __forceinline__ float2 unpack2(u64 v) {
    float2 r; asm("mov.b64 {%0, %1}, %2;" : "=f"(r.x), "=f"(r.y) : "l"(v)); return r;
}

// ---------------------------------------------------------------------------
// K0: transpose conv weights -> g_wt[t][c][o]   (o<512: Q, else K)
// ---------------------------------------------------------------------------
__global__ __launch_bounds__(256) void wt_transpose_kernel(
    const float* __restrict__ wq, const float* __restrict__ wk)
{
    int i = blockIdx.x * 256 + threadIdx.x;      // over 3*128*1024
    if (i >= KW * CC * 1024) return;
    int o = i & 1023;
    int c = (i >> 10) & 127;
    int t = i >> 17;
    g_wt[i] = (o < 512) ? wq[((size_t)o * CC + c) * KW + t]
                        : wk[((size_t)(o - 512) * CC + c) * KW + t];
}

// ---------------------------------------------------------------------------
// K1: causal conv projections for Q and K.  Tile 128s x 128o, 8x8/thread.
// grid = (o_tile 8, s_tile 16, b 4), block = 256
// Writes g_q/g_k in (b,h,d,s) layout.
// ---------------------------------------------------------------------------
__global__ __launch_bounds__(256) void qk_conv_kernel(
    const float* __restrict__ x,
    const float* __restrict__ bq, const float* __restrict__ bk)
{
    __shared__ __align__(16) float xs[CC][140];   // [c][s-window], rows s0-2..s0+127 (130 used)
    __shared__ __align__(16) float ws[32][128];   // [k][o]

    const int tid = threadIdx.x;
    const int tx = tid & 15, ty = tid >> 4;
    const int o0 = blockIdx.x * 128;
    const int s0 = blockIdx.y * 128;
    const int b  = blockIdx.z;

    // load x window transposed: xs[c][sl], sl in [0,130)
    for (int i = tid; i < CC * 130; i += 256) {
        int c = i & 127, sl = i >> 7;
        int s = s0 - 2 + sl;
        xs[c][sl] = (s >= 0) ? x[((size_t)b * SS + s) * CC + c] : 0.f;
    }

    u64 acc[8][4] = {};

    #pragma unroll
    for (int t = 0; t < KW; t++) {
        for (int cc = 0; cc < 4; cc++) {
            __syncthreads();
            // load ws[32][128] from g_wt, vectorized
            for (int i = tid; i < 1024; i += 256) {
                int kl = i >> 5, o4 = i & 31;
                ((float4*)&ws[kl][0])[o4] =
                    ((const float4*)&g_wt[((size_t)(t * CC + cc * 32 + kl)) * 1024 + o0])[o4];
            }
            __syncthreads();
            #pragma unroll 8
            for (int kl = 0; kl < 32; kl++) {
                const int c = cc * 32 + kl;
                float4 w0 = *(const float4*)&xs[c][ty * 8];
                float4 w1 = *(const float4*)&xs[c][ty * 8 + 4];
                float4 w2 = *(const float4*)&xs[c][ty * 8 + 8];
                float w[12] = { w0.x, w0.y, w0.z, w0.w, w1.x, w1.y, w1.z, w1.w,
                                w2.x, w2.y, w2.z, w2.w };
                u64 ap[8];
                #pragma unroll
                for (int i = 0; i < 8; i++) ap[i] = pack2(w[i + t]);
                ulonglong2 bA = *(const ulonglong2*)&ws[kl][tx * 8];
                ulonglong2 bB = *(const ulonglong2*)&ws[kl][tx * 8 + 4];
                #pragma unroll
                for (int i = 0; i < 8; i++) {
                    fma2(acc[i][0], ap[i], bA.x); fma2(acc[i][1], ap[i], bA.y);
                    fma2(acc[i][2], ap[i], bB.x); fma2(acc[i][3], ap[i], bB.y);
                }
            }
        }
    }

    // Epilogue: o-tile (128 wide) lies wholly in Q (o0<512) or K.
    const bool isq = (o0 < 512);
    const int obase = isq ? o0 : o0 - 512;
    float* dst = isq ? g_q : g_k;
    const float* bias = isq ? bq : bk;

    #pragma unroll
    for (int jp = 0; jp < 4; jp++) {
        float2 u[8];
        #pragma unroll
        for (int i = 0; i < 8; i++) u[i] = unpack2(acc[i][jp]);
        #pragma unroll
        for (int lane = 0; lane < 2; lane++) {
            const int oo = obase + tx * 8 + jp * 2 + lane;
            const float bsv = bias[oo];
            const int h = oo >> 6, d = oo & 63;
            float* p = &dst[(((size_t)b * HH + h) * DK_ + d) * SS + s0 + ty * 8];
            float4 r0, r1;
            if (lane == 0) {
                r0 = make_float4(u[0].x + bsv, u[1].x + bsv, u[2].x + bsv, u[3].x + bsv);
                r1 = make_float4(u[4].x + bsv, u[5].x + bsv, u[6].x + bsv, u[7].x + bsv);
            } else {
                r0 = make_float4(u[0].y + bsv, u[1].y + bsv, u[2].y + bsv, u[3].y + bsv);
                r1 = make_float4(u[4].y + bsv, u[5].y + bsv, u[6].y + bsv, u[7].y + bsv);
            }
            *(float4*)&p[0] = r0;
            *(float4*)&p[4] = r1;
        }
    }
}

// ---------------------------------------------------------------------------
// K2: V = relu(x @ wv^T + bv), stored as (b,h,s,d).
// grid = (o_tile 8, s_tile 128), block 256, 4x4/thread (small kernel)
// ---------------------------------------------------------------------------
__global__ __launch_bounds__(256) void v_proj_kernel(
    const float* __restrict__ x,
    const float* __restrict__ wv, const float* __restrict__ bv)
{
    __shared__ __align__(16) float Xs[32][68];
    __shared__ __align__(16) float Ws[32][68];
    const int tid = threadIdx.x, tx = tid & 15, ty = tid >> 4;
    const int o0 = blockIdx.x * 64;
    const int s0 = blockIdx.y * 64;   // global over B*S

    u64 acc[4][2] = {};

    for (int kc = 0; kc < CC; kc += 32) {
        __syncthreads();
        for (int i = tid; i < 2048; i += 256) {
            int kl = i & 31, r = i >> 5;
            Xs[kl][r] = x [((size_t)(s0 + r)) * CC + kc + kl];
            Ws[kl][r] = wv[((size_t)(o0 + r)) * CC + kc + kl];
        }
        __syncthreads();
        #pragma unroll
        for (int kk = 0; kk < 32; kk++) {
            float4 a4 = *(const float4*)&Xs[kk][ty * 4];
            ulonglong2 b2 = *(const ulonglong2*)&Ws[kk][tx * 4];
            u64 a0 = pack2(a4.x), a1 = pack2(a4.y), a2 = pack2(a4.z), a3 = pack2(a4.w);
            fma2(acc[0][0], a0, b2.x); fma2(acc[0][1], a0, b2.y);
            fma2(acc[1][0], a1, b2.x); fma2(acc[1][1], a1, b2.y);
            fma2(acc[2][0], a2, b2.x); fma2(acc[2][1], a2, b2.y);
            fma2(acc[3][0], a3, b2.x); fma2(acc[3][1], a3, b2.y);
        }
    }

    const int h = o0 >> 6;
    const float4 bias4 = *(const float4*)&bv[o0 + tx * 4];
    #pragma unroll
    for (int i = 0; i < 4; i++) {
        const int s = s0 + ty * 4 + i;
        const int bb = s >> 11, sl = s & (SS - 1);
        float2 p0 = unpack2(acc[i][0]), p1 = unpack2(acc[i][1]);
        float4 r = { fmaxf(p0.x + bias4.x, 0.f), fmaxf(p0.y + bias4.y, 0.f),
                     fmaxf(p1.x + bias4.z, 0.f), fmaxf(p1.y + bias4.w, 0.f) };
        *(float4*)&g_v[(((size_t)bb * HH + h) * SS + sl) * DV_ + tx * 4] = r;
    }
}

// ---------------------------------------------------------------------------
// K3: logits = Q K^T / 8, lower-triangle 128x128 tiles, 8x8/thread.
// grid = (kt 16, qt 16, bh 32), block 256
// ---------------------------------------------------------------------------
__global__ __launch_bounds__(256) void logits_kernel(float* __restrict__ score)
{
    const int kt = blockIdx.x, qt = blockIdx.y, bh = blockIdx.z;
    if (kt > qt) return;
    __shared__ __align__(16) float Qs[64][132];   // [d][q]
    __shared__ __align__(16) float Ks[64][132];   // [d][k]
    const int tid = threadIdx.x, tx = tid & 15, ty = tid >> 4;

    // fully vectorized, conflict-free loads from (b,h,d,s) layout
    for (int i = tid; i < 2048; i += 256) {
        int d = i >> 5, q4 = i & 31;
        ((float4*)&Qs[d][0])[q4] =
            *(const float4*)&g_q[((size_t)bh * DK_ + d) * SS + qt * 128 + q4 * 4];
        ((float4*)&Ks[d][0])[q4] =
            *(const float4*)&g_k[((size_t)bh * DK_ + d) * SS + kt * 128 + q4 * 4];
    }
    __syncthreads();

    u64 acc[4][8] = {};   // [q-pair][n]
    #pragma unroll 16
    for (int kk = 0; kk < 64; kk++) {
        ulonglong2 aA = *(const ulonglong2*)&Qs[kk][ty * 8];
        ulonglong2 aB = *(const ulonglong2*)&Qs[kk][ty * 8 + 4];
        float4 b0 = *(const float4*)&Ks[kk][tx * 8];
        float4 b1 = *(const float4*)&Ks[kk][tx * 8 + 4];
        u64 bp[8] = { pack2(b0.x), pack2(b0.y), pack2(b0.z), pack2(b0.w),
                      pack2(b1.x), pack2(b1.y), pack2(b1.z), pack2(b1.w) };
        #pragma unroll
        for (int n = 0; n < 8; n++) {
            fma2(acc[0][n], aA.x, bp[n]);
            fma2(acc[1][n], aA.y, bp[n]);
            fma2(acc[2][n], aB.x, bp[n]);
            fma2(acc[3][n], aB.y, bp[n]);
        }
    }

    #pragma unroll
    for (int qp = 0; qp < 4; qp++) {
        float2 u[8];
        #pragma unroll
        for (int n = 0; n < 8; n++) u[n] = unpack2(acc[qp][n]);
        #pragma unroll
        for (int lane = 0; lane < 2; lane++) {
            const int q = qt * 128 + ty * 8 + qp * 2 + lane;
            float* p = &score[((size_t)bh * SS + q) * SS + kt * 128 + tx * 8];
            float4 r0, r1;
            if (lane == 0) {
                r0 = make_float4(u[0].x, u[1].x, u[2].x, u[3].x);
                r1 = make_float4(u[4].x, u[5].x, u[6].x, u[7].x);
            } else {
                r0 = make_float4(u[0].y, u[1].y, u[2].y, u[3].y);
                r1 = make_float4(u[4].y, u[5].y, u[6].y, u[7].y);
            }
            r0.x *= 0.125f; r0.y *= 0.125f; r0.z *= 0.125f; r0.w *= 0.125f;
            r1.x *= 0.125f; r1.y *= 0.125f; r1.z *= 0.125f; r1.w *= 0.125f;
            *(float4*)&p[0] = r0;
            *(float4*)&p[4] = r1;
        }
    }
}

// ---------------------------------------------------------------------------
// K4: in-place row softmax over the causal prefix (DRAM-floor bound).
// ---------------------------------------------------------------------------
__global__ __launch_bounds__(256) void softmax_kernel(
    float* __restrict__ score, const int* __restrict__ length)
{
    const int row = blockIdx.x;            // 0 .. B*H*S-1
    const int q  = row & (SS - 1);
    const int bh = row >> 11;
    const int b  = bh >> 3;
    float* rp = score + (size_t)row * SS;
    const int tid = threadIdx.x;
    __shared__ float red[8];
    __shared__ float bc;

    if (q >= length[b]) {
        for (int k = tid; k < SS; k += 256) rp[k] = 0.f;
        return;
    }

    float v[8];
    float m = -1e30f;
    #pragma unroll
    for (int i = 0; i < 8; i++) {
        int k = tid + i * 256;
        v[i] = (k <= q) ? rp[k] : -1e30f;
        m = fmaxf(m, v[i]);
    }
    #pragma unroll
    for (int o = 16; o; o >>= 1) m = fmaxf(m, __shfl_xor_sync(0xffffffffu, m, o));
    if ((tid & 31) == 0) red[tid >> 5] = m;
    __syncthreads();
    if (tid == 0) {
        float t = red[0];
        #pragma unroll
        for (int w = 1; w < 8; w++) t = fmaxf(t, red[w]);
        bc = t;
    }
    __syncthreads();
    m = bc;

    float e[8];
    float sum = 0.f;
    #pragma unroll
    for (int i = 0; i < 8; i++) {
        int k = tid + i * 256;
        e[i] = (k <= q) ? __expf(v[i] - m) : 0.f;
        sum += e[i];
    }
    #pragma unroll
    for (int o = 16; o; o >>= 1) sum += __shfl_xor_sync(0xffffffffu, sum, o);
    __syncthreads();
    if ((tid & 31) == 0) red[tid >> 5] = sum;
    __syncthreads();
    if (tid == 0) {
        float t = 0.f;
        #pragma unroll
        for (int w = 0; w < 8; w++) t += red[w];
        bc = t;
    }
    __syncthreads();
    const float inv = 1.f / bc;
    #pragma unroll
    for (int i = 0; i < 8; i++) {
        int k = tid + i * 256;
        rp[k] = e[i] * inv;      // zeros for k > q
    }
}

// ---------------------------------------------------------------------------
// K5: out1 = P @ V, tile 128q x 64d, 8x4/thread, triangle-aware.
// grid = (qt 16, bh 32), block 256.  qt reversed for load balance.
// ---------------------------------------------------------------------------
__global__ __launch_bounds__(256) void pv_kernel(const float* __restrict__ score)
{
    const int qt = (int)gridDim.x - 1 - (int)blockIdx.x;
    const int bh = blockIdx.y;
    const int b = bh >> 3, h = bh & 7;
    __shared__ __align__(16) float Ps[64][132];   // [k][q]
    __shared__ __align__(16) float Vs[64][68];    // [k][d]
    const int tid = threadIdx.x, tx = tid & 15, ty = tid >> 4;

    u64 acc[4][4] = {};   // [q-pair][d]

    const int ntiles = 2 * qt + 2;   // k tiles of 64 covering k < (qt+1)*128
    for (int kt = 0; kt < ntiles; kt++) {
        __syncthreads();
        // P: 64k x 128q (transpose in smem; 4-way STS conflict, amortized)
        for (int i = tid; i < 8192; i += 256) {
            int c = i & 63, r = i >> 6;
            Ps[c][r] = score[((size_t)bh * SS + qt * 128 + r) * SS + kt * 64 + c];
        }
        // V: 64k x 64d, vectorized conflict-free
        for (int i = tid; i < 1024; i += 256) {
            int c4 = i & 15, r = i >> 4;
            ((float4*)&Vs[r][0])[c4] =
                *(const float4*)&g_v[((size_t)bh * SS + kt * 64 + r) * DV_ + c4 * 4];
        }
        __syncthreads();
        #pragma unroll 16
        for (int kk = 0; kk < 64; kk++) {
            ulonglong2 aA = *(const ulonglong2*)&Ps[kk][ty * 8];
            ulonglong2 aB = *(const ulonglong2*)&Ps[kk][ty * 8 + 4];
            float4 bv4 = *(const float4*)&Vs[kk][tx * 4];
            u64 b0 = pack2(bv4.x), b1 = pack2(bv4.y), b2 = pack2(bv4.z), b3 = pack2(bv4.w);
            fma2(acc[0][0], aA.x, b0); fma2(acc[0][1], aA.x, b1); fma2(acc[0][2], aA.x, b2); fma2(acc[0][3], aA.x, b3);
            fma2(acc[1][0], aA.y, b0); fma2(acc[1][1], aA.y, b1); fma2(acc[1][2], aA.y, b2); fma2(acc[1][3], aA.y, b3);
            fma2(acc[2][0], aB.x, b0); fma2(acc[2][1], aB.x, b1); fma2(acc[2][2], aB.x, b2); fma2(acc[2][3], aB.x, b3);
            fma2(acc[3][0], aB.y, b0); fma2(acc[3][1], aB.y, b1); fma2(acc[3][2], aB.y, b2); fma2(acc[3][3], aB.y, b3);
        }
    }

    #pragma unroll
    for (int qp = 0; qp < 4; qp++) {
        float2 u[4];
        #pragma unroll
        for (int n = 0; n < 4; n++) u[n] = unpack2(acc[qp][n]);
        #pragma unroll
        for (int lane = 0; lane < 2; lane++) {
            const int s = qt * 128 + ty * 8 + qp * 2 + lane;
            float4 r = (lane == 0)
                ? make_float4(u[0].x, u[1].x, u[2].x, u[3].x)
                : make_float4(u[0].y, u[1].y, u[2].y, u[3].y);
            *(float4*)&g_o1[(((size_t)b * SS + s) * HH + h) * DV_ + tx * 4] = r;
        }
    }
}

// ---------------------------------------------------------------------------
// K6: out3 = relu(out2 @ w1^T + b1) @ w2^T + b2
// ---------------------------------------------------------------------------
__global__ __launch_bounds__(256) void mlp_kernel(
    const float* __restrict__ w1, const float* __restrict__ b1,
    const float* __restrict__ w2, const float* __restrict__ b2,
    float* __restrict__ out3)
{
    __shared__ __align__(16) float Os [32][68];   // [kl][s]
    __shared__ __align__(16) float W1s[32][68];   // [kl][j]
    __shared__ __align__(16) float hids[64][68];  // [s][j]
    const int tid = threadIdx.x, tx = tid & 15, ty = tid >> 4;
    const int s0 = blockIdx.x * 64;

    u64 acc[4][2] = {};

    for (int kc = 0; kc < 512; kc += 32) {
        __syncthreads();
        for (int i = tid; i < 2048; i += 256) {
            int kl = i & 31, r = i >> 5;
            Os [kl][r] = g_o1[((size_t)(s0 + r)) * 512 + kc + kl];
            W1s[kl][r] = w1 [((size_t)r) * 512 + kc + kl];
        }
        __syncthreads();
        #pragma unroll
        for (int kk = 0; kk < 32; kk++) {
            float4 a4 = *(const float4*)&Os [kk][ty * 4];
            ulonglong2 b2v = *(const ulonglong2*)&W1s[kk][tx * 4];
            u64 a0 = pack2(a4.x), a1 = pack2(a4.y), a2 = pack2(a4.z), a3 = pack2(a4.w);
            fma2(acc[0][0], a0, b2v.x); fma2(acc[0][1], a0, b2v.y);
            fma2(acc[1][0], a1, b2v.x); fma2(acc[1][1], a1, b2v.y);
            fma2(acc[2][0], a2, b2v.x); fma2(acc[2][1], a2, b2v.y);
            fma2(acc[3][0], a3, b2v.x); fma2(acc[3][1], a3, b2v.y);
        }
    }

    const float4 b14 = *(const float4*)&b1[tx * 4];
    #pragma unroll
    for (int i = 0; i < 4; i++) {
        float2 p0 = unpack2(acc[i][0]), p1 = unpack2(acc[i][1]);
        float4 r = { fmaxf(p0.x + b14.x, 0.f), fmaxf(p0.y + b14.y, 0.f),
                     fmaxf(p1.x + b14.z, 0.f), fmaxf(p1.y + b14.w, 0.f) };
        *(float4*)&hids[ty * 4 + i][tx * 4] = r;
    }
    __syncthreads();

    if (tid < 64) {
        float sum = 0.f;
        #pragma unroll 8
        for (int j = 0; j < 64; j++) sum += hids[tid][j] * w2[j];
        out3[s0 + tid] = sum + b2[0];
    }
}

// ---------------------------------------------------------------------------
extern "C" void kernel_launch(void* const* d_in, const int* in_sizes, int n_in,
                              void* d_out, int out_size)
{
    const float* x      = (const float*)d_in[0];
    const int*   length = (const int*)  d_in[1];
    const float* wq     = (const float*)d_in[2];
    const float* bq     = (const float*)d_in[3];
    const float* wk     = (const float*)d_in[4];
    const float* bk     = (const float*)d_in[5];
    const float* wv     = (const float*)d_in[6];
    const float* bv     = (const float*)d_in[7];
    const float* w1     = (const float*)d_in[8];
    const float* b1     = (const float*)d_in[9];
    const float* w2     = (const float*)d_in[10];
    const float* b2     = (const float*)d_in[11];

    float* out   = (float*)d_out;
    float* out3  = out;                       // (B,S,1) = 8192 elements
    float* score = out + (size_t)BB * SS;     // (B,H,S,S)

    wt_transpose_kernel<<<(KW * CC * 1024 + 255) / 256, 256>>>(wq, wk);
    qk_conv_kernel<<<dim3(8, 16, BB), 256>>>(x, bq, bk);
    v_proj_kernel <<<dim3(8, 128),    256>>>(x, wv, bv);
    logits_kernel <<<dim3(16, 16, 32), 256>>>(score);
    softmax_kernel<<<BB * HH * SS,    256>>>(score, length);
    pv_kernel     <<<dim3(16, 32),    256>>>(score);
    mlp_kernel    <<<128,             256>>>(w1, b1, w2, b2, out3);
}